// round 6
// baseline (speedup 1.0000x reference)
#include <cuda_runtime.h>

#define NSEG 128
#define EDIM 128
#define NHEAD 4
#define WARPS_PER_BLK 8
#define RPW 28   // rows per warp, even

__device__ float g_s[NSEG * NHEAD];
__device__ float g_acc[NSEG * NHEAD * EDIM];
__device__ int   g_is64;
__device__ unsigned int g_done;

__global__ void zero_kernel(const int* __restrict__ b32, int N) {
    int i = blockIdx.x * blockDim.x + threadIdx.x;
    if (i < NSEG * NHEAD * EDIM) g_acc[i] = 0.0f;
    if (i < NSEG * NHEAD)        g_s[i]   = 0.0f;
    if (i == 0) {
        g_done = 0;
        // int64 (LE): int32 view's high words at the tail are zero.
        int a = b32[N - 1];
        int b = (N >= 3) ? b32[N - 3] : 1;
        int c = (N >= 5) ? b32[N - 5] : 1;
        g_is64 = (a == 0 && b == 0 && c == 0) ? 1 : 0;
    }
}

// Flush this lane's accumulators for segment `cur`.
#define FLUSH()                                                                  \
    {                                                                            \
        if (j == 0) {                                                            \
            atomicAdd(&g_s[cur * NHEAD + 0], accS0);                             \
            atomicAdd(&g_s[cur * NHEAD + 1], accS1);                             \
            atomicAdd(&g_s[cur * NHEAD + 2], accS2);                             \
            atomicAdd(&g_s[cur * NHEAD + 3], accS3);                             \
        }                                                                        \
        _Pragma("unroll")                                                        \
        for (int h = 0; h < NHEAD; ++h) {                                        \
            float* bA = &g_acc[(cur * NHEAD + h) * EDIM + j * 4];                \
            atomicAdd(bA + 0, a0[h].x);                                          \
            atomicAdd(bA + 1, a0[h].y);                                          \
            atomicAdd(bA + 2, a0[h].z);                                          \
            atomicAdd(bA + 3, a0[h].w);                                          \
            float* bB = &g_acc[(cur * NHEAD + h) * EDIM + (j + 16) * 4];         \
            atomicAdd(bB + 0, a1[h].x);                                          \
            atomicAdd(bB + 1, a1[h].y);                                          \
            atomicAdd(bB + 2, a1[h].z);                                          \
            atomicAdd(bB + 3, a1[h].w);                                          \
        }                                                                        \
    }

__global__ __launch_bounds__(256) void att_kernel(
    const float4* __restrict__ x,        // [N, 32] float4 view of [N,128]
    const float4* __restrict__ w,        // [4, 32]
    const void*   __restrict__ batch,
    float* __restrict__ out, int N)
{
    __shared__ float4 w_s[NHEAD][32];
    __shared__ int s_last;

    const int t    = threadIdx.x;
    const int lane = t & 31;
    const int wid  = t >> 5;
    const int grp  = lane >> 4;    // which of the 2 rows this lane serves
    const int j    = lane & 15;    // col-quad index within the row (0..15)
    const int is64 = g_is64;

    if (t < NHEAD * 32) ((float4*)w_s)[t] = w[t];
    __syncthreads();

    const int gw  = blockIdx.x * WARPS_PER_BLK + wid;
    int beg = gw * RPW;
    int end = beg + RPW; if (end > N) end = N;

    if (beg < N) {
        const long long* b64 = (const long long*)batch;
        const int*       b32 = (const int*)batch;

        float4 a0[NHEAD], a1[NHEAD];
        float accS0 = 0.f, accS1 = 0.f, accS2 = 0.f, accS3 = 0.f;
#pragma unroll
        for (int h = 0; h < NHEAD; ++h) {
            a0[h] = make_float4(0, 0, 0, 0);
            a1[h] = make_float4(0, 0, 0, 0);
        }

        int cur = (is64 ? (int)b64[beg] : b32[beg]) & (NSEG - 1);

        for (int n = beg; n < end; n += 2) {
            const int  myrow = n + grp;
            const bool valid = myrow < end;
            const int  rc    = valid ? myrow : end - 1;

            int seg = (is64 ? (int)b64[rc] : b32[rc]) & (NSEG - 1);
            if (valid && seg != cur) {
                FLUSH();
#pragma unroll
                for (int h = 0; h < NHEAD; ++h) {
                    a0[h] = make_float4(0, 0, 0, 0);
                    a1[h] = make_float4(0, 0, 0, 0);
                }
                accS0 = accS1 = accS2 = accS3 = 0.f;
                cur = seg;
            }

            const float4* xr = x + (size_t)rc * 32;
            float4 xa = xr[j];
            float4 xb = xr[j + 16];

            // per-lane partial dots over this lane's 8 columns, 4 heads
            float4 wa, wb;
            wa = w_s[0][j]; wb = w_s[0][j + 16];
            float p0 = xa.x*wa.x + xa.y*wa.y + xa.z*wa.z + xa.w*wa.w
                     + xb.x*wb.x + xb.y*wb.y + xb.z*wb.z + xb.w*wb.w;
            wa = w_s[1][j]; wb = w_s[1][j + 16];
            float p1 = xa.x*wa.x + xa.y*wa.y + xa.z*wa.z + xa.w*wa.w
                     + xb.x*wb.x + xb.y*wb.y + xb.z*wb.z + xb.w*wb.w;
            wa = w_s[2][j]; wb = w_s[2][j + 16];
            float p2 = xa.x*wa.x + xa.y*wa.y + xa.z*wa.z + xa.w*wa.w
                     + xb.x*wb.x + xb.y*wb.y + xb.z*wb.z + xb.w*wb.w;
            wa = w_s[3][j]; wb = w_s[3][j + 16];
            float p3 = xa.x*wa.x + xa.y*wa.y + xa.z*wa.z + xa.w*wa.w
                     + xb.x*wb.x + xb.y*wb.y + xb.z*wb.z + xb.w*wb.w;

            // butterfly within each 16-lane group (offsets 1,2,4,8)
#pragma unroll
            for (int off = 1; off < 16; off <<= 1) {
                p0 += __shfl_xor_sync(0xffffffffu, p0, off);
                p1 += __shfl_xor_sync(0xffffffffu, p1, off);
                p2 += __shfl_xor_sync(0xffffffffu, p2, off);
                p3 += __shfl_xor_sync(0xffffffffu, p3, off);
            }

            float e0 = valid ? __expf(p0) : 0.f;
            float e1 = valid ? __expf(p1) : 0.f;
            float e2 = valid ? __expf(p2) : 0.f;
            float e3 = valid ? __expf(p3) : 0.f;

            accS0 += e0; accS1 += e1; accS2 += e2; accS3 += e3;

            a0[0].x += e0*xa.x; a0[0].y += e0*xa.y; a0[0].z += e0*xa.z; a0[0].w += e0*xa.w;
            a1[0].x += e0*xb.x; a1[0].y += e0*xb.y; a1[0].z += e0*xb.z; a1[0].w += e0*xb.w;
            a0[1].x += e1*xa.x; a0[1].y += e1*xa.y; a0[1].z += e1*xa.z; a0[1].w += e1*xa.w;
            a1[1].x += e1*xb.x; a1[1].y += e1*xb.y; a1[1].z += e1*xb.z; a1[1].w += e1*xb.w;
            a0[2].x += e2*xa.x; a0[2].y += e2*xa.y; a0[2].z += e2*xa.z; a0[2].w += e2*xa.w;
            a1[2].x += e2*xb.x; a1[2].y += e2*xb.y; a1[2].z += e2*xb.z; a1[2].w += e2*xb.w;
            a0[3].x += e3*xa.x; a0[3].y += e3*xa.y; a0[3].z += e3*xa.z; a0[3].w += e3*xa.w;
            a1[3].x += e3*xb.x; a1[3].y += e3*xb.y; a1[3].z += e3*xb.z; a1[3].w += e3*xb.w;
        }

        FLUSH();
    }

    // ---- inline finalize: last block reduces ----
    __threadfence();
    __syncthreads();
    if (t == 0) {
        unsigned int prev = atomicAdd(&g_done, 1u);
        s_last = (prev == (unsigned int)(gridDim.x - 1)) ? 1 : 0;
    }
    __syncthreads();
    if (s_last) {
        for (int i = t; i < NSEG * EDIM; i += 256) {
            int b = i >> 7;
            int e = i & 127;
            float r = 0.0f;
#pragma unroll
            for (int h = 0; h < NHEAD; ++h) {
                float av = __ldcg(&g_acc[(b * NHEAD + h) * EDIM + e]);
                float sv = __ldcg(&g_s[b * NHEAD + h]);
                r += av / sv;
            }
            out[i] = r * (1.0f / NHEAD);
        }
    }
}

extern "C" void kernel_launch(void* const* d_in, const int* in_sizes, int n_in,
                              void* d_out, int out_size) {
    const float* x     = (const float*)d_in[0];
    const float* w     = (const float*)d_in[1];
    const void*  batch = d_in[2];

    int N = in_sizes[0] / EDIM;
    int warps = (N + RPW - 1) / RPW;
    int nblk  = (warps + WARPS_PER_BLK - 1) / WARPS_PER_BLK;

    zero_kernel<<<(NSEG * NHEAD * EDIM + 255) / 256, 256>>>((const int*)batch, N);
    att_kernel<<<nblk, 256>>>((const float4*)x, (const float4*)w, batch,
                              (float*)d_out, N);
}

// round 7
// speedup vs baseline: 2.3294x; 2.3294x over previous
#include <cuda_runtime.h>

#define NSEG 128
#define EDIM 128
#define NHEAD 4
#define WARPS_PER_BLK 8
#define NBLK 1184   // 8 blocks/SM * 148 SMs

// Scratch: per-(segment,head) exp-sum and weighted-x accumulator.
__device__ float g_s[NSEG * NHEAD];
__device__ float g_acc[NSEG * NHEAD * EDIM];
__device__ int   g_is64;

__global__ void detect_kernel(const int* __restrict__ b32, int N) {
    int a = b32[N - 1];
    int b = (N >= 3) ? b32[N - 3] : 1;
    int c = (N >= 5) ? b32[N - 5] : 1;
    g_is64 = (a == 0 && b == 0 && c == 0) ? 1 : 0;
}

__global__ void zero_kernel() {
    int i = blockIdx.x * blockDim.x + threadIdx.x;
    if (i < NSEG * NHEAD * EDIM) g_acc[i] = 0.0f;
    if (i < NSEG * NHEAD)        g_s[i]   = 0.0f;
}

__device__ __forceinline__ int load_seg(const void* batch, int n, int is64) {
    int v;
    if (is64) v = (int)((const long long*)batch)[n];
    else      v = ((const int*)batch)[n];
    return v & (NSEG - 1);
}

__global__ __launch_bounds__(256) void att_kernel(
    const float4* __restrict__ x,        // [N, 32] float4 view of [N,128]
    const float4* __restrict__ w,        // [4, 32]
    const void*   __restrict__ batch,    // [N] sorted segment ids
    int N, int rpw)
{
    const int lane = threadIdx.x & 31;
    const int wid  = threadIdx.x >> 5;
    const int gw   = blockIdx.x * WARPS_PER_BLK + wid;
    int beg = gw * rpw;
    if (beg >= N) return;
    int end = beg + rpw; if (end > N) end = N;

    const int is64 = g_is64;

    float4 wv[NHEAD];
#pragma unroll
    for (int h = 0; h < NHEAD; ++h) wv[h] = w[h * 32 + lane];

    float  accS[NHEAD];
    float4 accA[NHEAD];
#pragma unroll
    for (int h = 0; h < NHEAD; ++h) {
        accS[h] = 0.0f;
        accA[h] = make_float4(0.0f, 0.0f, 0.0f, 0.0f);
    }

    int cur = load_seg(batch, beg, is64);

    // ---- software pipeline: prefetch row n+1 while processing row n ----
    float4 xv_next = x[(size_t)beg * 32 + lane];
    int    seg_next = cur;

    for (int n = beg; n < end; ++n) {
        float4 xv  = xv_next;
        int    seg = seg_next;
        if (n + 1 < end) {
            xv_next  = x[(size_t)(n + 1) * 32 + lane];
            seg_next = load_seg(batch, n + 1, is64);
        }

        if (seg != cur) {
            if (lane == 0) {
#pragma unroll
                for (int h = 0; h < NHEAD; ++h)
                    atomicAdd(&g_s[cur * NHEAD + h], accS[h]);
            }
#pragma unroll
            for (int h = 0; h < NHEAD; ++h) {
                float* dst = &g_acc[(cur * NHEAD + h) * EDIM + lane * 4];
                atomicAdd(dst + 0, accA[h].x);
                atomicAdd(dst + 1, accA[h].y);
                atomicAdd(dst + 2, accA[h].z);
                atomicAdd(dst + 3, accA[h].w);
                accA[h] = make_float4(0.0f, 0.0f, 0.0f, 0.0f);
                accS[h] = 0.0f;
            }
            cur = seg;
        }

        float p[NHEAD];
#pragma unroll
        for (int h = 0; h < NHEAD; ++h)
            p[h] = xv.x * wv[h].x + xv.y * wv[h].y + xv.z * wv[h].z + xv.w * wv[h].w;

#pragma unroll
        for (int off = 16; off > 0; off >>= 1) {
#pragma unroll
            for (int h = 0; h < NHEAD; ++h)
                p[h] += __shfl_xor_sync(0xffffffffu, p[h], off);
        }

#pragma unroll
        for (int h = 0; h < NHEAD; ++h) {
            float e = __expf(p[h]);
            accS[h]  += e;
            accA[h].x += e * xv.x;
            accA[h].y += e * xv.y;
            accA[h].z += e * xv.z;
            accA[h].w += e * xv.w;
        }
    }

    if (lane == 0) {
#pragma unroll
        for (int h = 0; h < NHEAD; ++h)
            atomicAdd(&g_s[cur * NHEAD + h], accS[h]);
    }
#pragma unroll
    for (int h = 0; h < NHEAD; ++h) {
        float* dst = &g_acc[(cur * NHEAD + h) * EDIM + lane * 4];
        atomicAdd(dst + 0, accA[h].x);
        atomicAdd(dst + 1, accA[h].y);
        atomicAdd(dst + 2, accA[h].z);
        atomicAdd(dst + 3, accA[h].w);
    }
}

__global__ void finalize_kernel(float* __restrict__ out) {
    int b = blockIdx.x;
    int e = threadIdx.x;
    float r = 0.0f;
#pragma unroll
    for (int h = 0; h < NHEAD; ++h)
        r += g_acc[(b * NHEAD + h) * EDIM + e] / g_s[b * NHEAD + h];
    out[b * EDIM + e] = r * (1.0f / NHEAD);
}

extern "C" void kernel_launch(void* const* d_in, const int* in_sizes, int n_in,
                              void* d_out, int out_size) {
    const float* x     = (const float*)d_in[0];
    const float* w     = (const float*)d_in[1];
    const void*  batch = d_in[2];

    int N = in_sizes[0] / EDIM;
    int warps = NBLK * WARPS_PER_BLK;
    int rpw = (N + warps - 1) / warps;

    detect_kernel<<<1, 1>>>((const int*)batch, N);
    zero_kernel<<<(NSEG * NHEAD * EDIM + 255) / 256, 256>>>();
    att_kernel<<<NBLK, 256>>>((const float4*)x, (const float4*)w, batch, N, rpw);
    finalize_kernel<<<NSEG, EDIM>>>((float*)d_out);
}